// round 2
// baseline (speedup 1.0000x reference)
#include <cuda_runtime.h>
#include <math.h>
#include <stdint.h>

#define B_   32
#define S_   64
#define E_   512
#define H_   1024
#define V_   32000
#define G3H  (3 * H_)
#define NTOK (B_ * S_)
#define BH   (B_ * H_)

// ---------------- scratch (device globals; no allocation allowed) ----------------
__device__ float g_ex[NTOK * E_];     // encoder embeddings  [2048, 512]
__device__ float g_dx[NTOK * E_];     // decoder embeddings  [2048, 512]
__device__ float g_xg[NTOK * G3H];    // precomputed input gates [2048, 3072]
__device__ float g_seqA[NTOK * H_];   // sequence buffer (y0 / d0)
__device__ float g_seqB[NTOK * H_];   // sequence buffer (d1)
__device__ float g_h[8][BH];          // 4 layers x ping-pong hidden state [32,1024]

// ---------------- embedding gather ----------------
__global__ void embed_kernel(const int* __restrict__ idx,
                             const float* __restrict__ emb,
                             float* __restrict__ out) {
    int tok = blockIdx.x;
    int row = idx[tok];
    const float4* src = (const float4*)(emb + (size_t)row * E_);
    float4* dst = (float4*)(out + (size_t)tok * E_);
    for (int i = threadIdx.x; i < E_ / 4; i += blockDim.x) dst[i] = src[i];
}

// ---------------- tf32 tensor-core GEMM ----------------
// C[M,N] = A[M,K] * W[N,K]^T + bias[N]
// Both operands K-major fp32 in GMEM; converted to tf32 at SMEM fill.
// Block tile 128x128, BK=16, 256 threads = 8 warps (2m x 4n), warp tile 64x32.
// mma.sync.m16n8k8.row.col.f32.tf32.tf32.f32
// Requires M%128==0, N%128==0, K%16==0 (holds for all uses).

#define BM 128
#define BN 128
#define BK 16
#define LDS_ 132   // padded leading dim (k-major smem rows of 132 words)

__device__ __forceinline__ uint32_t f2tf32(float f) {
    uint32_t r;
    asm("cvt.rna.tf32.f32 %0, %1;" : "=r"(r) : "f"(f));
    return r;
}

__device__ __forceinline__ void mma_tf32(float c[4],
                                         uint32_t a0, uint32_t a1, uint32_t a2, uint32_t a3,
                                         uint32_t b0, uint32_t b1) {
    asm volatile(
        "mma.sync.aligned.m16n8k8.row.col.f32.tf32.tf32.f32 "
        "{%0,%1,%2,%3}, {%4,%5,%6,%7}, {%8,%9}, {%0,%1,%2,%3};"
        : "+f"(c[0]), "+f"(c[1]), "+f"(c[2]), "+f"(c[3])
        : "r"(a0), "r"(a1), "r"(a2), "r"(a3), "r"(b0), "r"(b1));
}

__global__ __launch_bounds__(256)
void mma_gemm_kernel(const float* __restrict__ A,
                     const float* __restrict__ W,
                     const float* __restrict__ bias,
                     float* __restrict__ C,
                     int M, int N, int K) {
    __shared__ uint32_t As[BK * LDS_];
    __shared__ uint32_t Ws[BK * LDS_];

    const int tid  = threadIdx.x;
    const int lane = tid & 31;
    const int warp = tid >> 5;
    const int wm   = (warp & 1) * 64;   // warp m offset in tile
    const int wn   = (warp >> 1) * 32;  // warp n offset in tile

    const int bm = blockIdx.y * BM;
    const int bn = blockIdx.x * BN;

    // global load mapping: 2 float4 per thread per tile
    const int lrow = tid & 127;          // row within 128-tall tile
    const int kq   = (tid >> 7) * 4;     // 0 or 4; this thread covers k-quads {kq, kq+8}

    const float* Ag = A + (size_t)(bm + lrow) * K + kq;
    const float* Wg = W + (size_t)(bn + lrow) * K + kq;

    float acc[4][4][4];
#pragma unroll
    for (int i = 0; i < 4; i++)
#pragma unroll
        for (int j = 0; j < 4; j++)
#pragma unroll
            for (int c = 0; c < 4; c++) acc[i][j][c] = 0.f;

    // prefetch first tile
    float4 ra0 = *(const float4*)(Ag);
    float4 ra1 = *(const float4*)(Ag + 8);
    float4 rw0 = *(const float4*)(Wg);
    float4 rw1 = *(const float4*)(Wg + 8);

    const int lk = lane & 3;   // fragment k within quad
    const int lg = lane >> 2;  // fragment group (m for A, n for B)

    for (int k0 = 0; k0 < K; k0 += BK) {
        // stage current tile into smem (convert to tf32, transpose to [k][row])
        As[(kq + 0) * LDS_ + lrow] = f2tf32(ra0.x);
        As[(kq + 1) * LDS_ + lrow] = f2tf32(ra0.y);
        As[(kq + 2) * LDS_ + lrow] = f2tf32(ra0.z);
        As[(kq + 3) * LDS_ + lrow] = f2tf32(ra0.w);
        As[(kq + 8) * LDS_ + lrow] = f2tf32(ra1.x);
        As[(kq + 9) * LDS_ + lrow] = f2tf32(ra1.y);
        As[(kq +10) * LDS_ + lrow] = f2tf32(ra1.z);
        As[(kq +11) * LDS_ + lrow] = f2tf32(ra1.w);
        Ws[(kq + 0) * LDS_ + lrow] = f2tf32(rw0.x);
        Ws[(kq + 1) * LDS_ + lrow] = f2tf32(rw0.y);
        Ws[(kq + 2) * LDS_ + lrow] = f2tf32(rw0.z);
        Ws[(kq + 3) * LDS_ + lrow] = f2tf32(rw0.w);
        Ws[(kq + 8) * LDS_ + lrow] = f2tf32(rw1.x);
        Ws[(kq + 9) * LDS_ + lrow] = f2tf32(rw1.y);
        Ws[(kq +10) * LDS_ + lrow] = f2tf32(rw1.z);
        Ws[(kq +11) * LDS_ + lrow] = f2tf32(rw1.w);
        __syncthreads();

        // prefetch next tile (overlaps with MMA below)
        if (k0 + BK < K) {
            ra0 = *(const float4*)(Ag + k0 + BK);
            ra1 = *(const float4*)(Ag + k0 + BK + 8);
            rw0 = *(const float4*)(Wg + k0 + BK);
            rw1 = *(const float4*)(Wg + k0 + BK + 8);
        }

#pragma unroll
        for (int kk = 0; kk < BK; kk += 8) {
            const int kr = kk + lk;
            uint32_t af[4][4];
#pragma unroll
            for (int mt = 0; mt < 4; mt++) {
                int mb = wm + mt * 16 + lg;
                af[mt][0] = As[(kr)     * LDS_ + mb];
                af[mt][1] = As[(kr)     * LDS_ + mb + 8];
                af[mt][2] = As[(kr + 4) * LDS_ + mb];
                af[mt][3] = As[(kr + 4) * LDS_ + mb + 8];
            }
            uint32_t bf[4][2];
#pragma unroll
            for (int nt = 0; nt < 4; nt++) {
                int nb = wn + nt * 8 + lg;
                bf[nt][0] = Ws[(kr)     * LDS_ + nb];
                bf[nt][1] = Ws[(kr + 4) * LDS_ + nb];
            }
#pragma unroll
            for (int mt = 0; mt < 4; mt++)
#pragma unroll
                for (int nt = 0; nt < 4; nt++)
                    mma_tf32(acc[mt][nt],
                             af[mt][0], af[mt][1], af[mt][2], af[mt][3],
                             bf[nt][0], bf[nt][1]);
        }
        __syncthreads();
    }

    // epilogue: bias + store (fragment layout: c0/c1 at row, c2/c3 at row+8)
#pragma unroll
    for (int mt = 0; mt < 4; mt++) {
#pragma unroll
        for (int nt = 0; nt < 4; nt++) {
            int m0 = bm + wm + mt * 16 + lg;
            int n0 = bn + wn + nt * 8 + (lane & 3) * 2;
            float b0v = bias[n0];
            float b1v = bias[n0 + 1];
            float2 o0 = make_float2(acc[mt][nt][0] + b0v, acc[mt][nt][1] + b1v);
            float2 o1 = make_float2(acc[mt][nt][2] + b0v, acc[mt][nt][3] + b1v);
            *(float2*)(C + (size_t)m0 * N + n0)       = o0;
            *(float2*)(C + (size_t)(m0 + 8) * N + n0) = o1;
        }
    }
}

// ---------------- fused GRU time step ----------------
__global__ __launch_bounds__(256)
void gru_step_kernel(const float* __restrict__ h_prev,
                     const float* __restrict__ Whh,
                     const float* __restrict__ bhh,
                     const float* __restrict__ xg,
                     int t, int zero_init,
                     float* __restrict__ h_next,
                     float* __restrict__ y) {
    extern __shared__ float h_s[];   // [H_][B_] = 1024 x 32 floats = 128 KB

    const int tid = threadIdx.x;
    const int b = tid & 31;
    const int j = (blockIdx.x << 3) + (tid >> 5);

    float accr = bhh[j];
    float accz = bhh[H_ + j];
    float accn = bhh[2 * H_ + j];
    float h_old = 0.f;

    if (!zero_init) {
        // cooperative transpose-load of h into smem
        for (int i4 = tid; i4 < BH / 4; i4 += 256) {
            int lin = i4 * 4;
            int bb = lin >> 10;            // /H_
            int kk = lin & (H_ - 1);
            float4 v = *(const float4*)(h_prev + lin);
            h_s[(kk + 0) * B_ + bb] = v.x;
            h_s[(kk + 1) * B_ + bb] = v.y;
            h_s[(kk + 2) * B_ + bb] = v.z;
            h_s[(kk + 3) * B_ + bb] = v.w;
        }
        __syncthreads();

        const float* wr = Whh + (size_t)j * H_;
        const float* wz = Whh + (size_t)(H_ + j) * H_;
        const float* wn = Whh + (size_t)(2 * H_ + j) * H_;

#pragma unroll 8
        for (int k = 0; k < H_; k += 4) {
            float4 r4 = __ldg((const float4*)(wr + k));
            float4 z4 = __ldg((const float4*)(wz + k));
            float4 n4 = __ldg((const float4*)(wn + k));
            float h0 = h_s[(k + 0) * B_ + b];
            float h1 = h_s[(k + 1) * B_ + b];
            float h2 = h_s[(k + 2) * B_ + b];
            float h3 = h_s[(k + 3) * B_ + b];
            accr += h0 * r4.x + h1 * r4.y + h2 * r4.z + h3 * r4.w;
            accz += h0 * z4.x + h1 * z4.y + h2 * z4.z + h3 * z4.w;
            accn += h0 * n4.x + h1 * n4.y + h2 * n4.z + h3 * n4.w;
        }
        h_old = h_s[j * B_ + b];
    }

    const float* xp = xg + ((size_t)b * S_ + t) * G3H;
    float r = 1.f / (1.f + expf(-(xp[j] + accr)));
    float z = 1.f / (1.f + expf(-(xp[H_ + j] + accz)));
    float n = tanhf(xp[2 * H_ + j] + r * accn);
    float hnew = (1.f - z) * n + z * h_old;

    h_next[b * H_ + j] = hnew;
    if (y) y[((size_t)b * S_ + t) * H_ + j] = hnew;
}

// ---------------- driver ----------------
static void run_scan(const float* Whh, const float* bhh, const float* xg,
                     float* hpair, const float* h_init, int zero0, float* yout) {
    for (int t = 0; t < S_; t++) {
        const float* hin;
        int zi = 0;
        if (t == 0) {
            if (zero0) { hin = hpair; zi = 1; }
            else       { hin = h_init; }
        } else {
            hin = hpair + (t & 1) * BH;
        }
        float* hout = hpair + ((t + 1) & 1) * BH;
        gru_step_kernel<<<128, 256, 131072>>>(hin, Whh, bhh, xg, t, zi, hout, yout);
    }
}

extern "C" void kernel_launch(void* const* d_in, const int* in_sizes, int n_in,
                              void* d_out, int out_size) {
    const int*   enc_X   = (const int*)d_in[0];
    const int*   dec_X   = (const int*)d_in[1];
    const float* emb_enc = (const float*)d_in[2];
    const float* emb_dec = (const float*)d_in[3];
    const float* eW0i = (const float*)d_in[4];
    const float* eW0h = (const float*)d_in[5];
    const float* eb0i = (const float*)d_in[6];
    const float* eb0h = (const float*)d_in[7];
    const float* eW1i = (const float*)d_in[8];
    const float* eW1h = (const float*)d_in[9];
    const float* eb1i = (const float*)d_in[10];
    const float* eb1h = (const float*)d_in[11];
    const float* dW0i = (const float*)d_in[12];
    const float* dW0h = (const float*)d_in[13];
    const float* db0i = (const float*)d_in[14];
    const float* db0h = (const float*)d_in[15];
    const float* dW1i = (const float*)d_in[16];
    const float* dW1h = (const float*)d_in[17];
    const float* db1i = (const float*)d_in[18];
    const float* db1h = (const float*)d_in[19];
    const float* fcW  = (const float*)d_in[20];
    const float* fcb  = (const float*)d_in[21];
    float* out = (float*)d_out;

    float *ex, *dx, *xg, *seqA, *seqB, *hb;
    cudaGetSymbolAddress((void**)&ex,   g_ex);
    cudaGetSymbolAddress((void**)&dx,   g_dx);
    cudaGetSymbolAddress((void**)&xg,   g_xg);
    cudaGetSymbolAddress((void**)&seqA, g_seqA);
    cudaGetSymbolAddress((void**)&seqB, g_seqB);
    cudaGetSymbolAddress((void**)&hb,   g_h);

    cudaFuncSetAttribute(gru_step_kernel,
                         cudaFuncAttributeMaxDynamicSharedMemorySize, 131072);

    // embeddings
    embed_kernel<<<NTOK, 128>>>(enc_X, emb_enc, ex);
    embed_kernel<<<NTOK, 128>>>(dec_X, emb_dec, dx);

    dim3 gemm_grid_3h(G3H / BN, NTOK / BM);

    // encoder layer 0
    mma_gemm_kernel<<<gemm_grid_3h, 256>>>(ex, eW0i, eb0i, xg, NTOK, G3H, E_);
    run_scan(eW0h, eb0h, xg, hb + 0 * 2 * BH, nullptr, 1, seqA);

    // encoder layer 1 (only final hidden needed)
    mma_gemm_kernel<<<gemm_grid_3h, 256>>>(seqA, eW1i, eb1i, xg, NTOK, G3H, H_);
    run_scan(eW1h, eb1h, xg, hb + 1 * 2 * BH, nullptr, 1, nullptr);

    // decoder layer 0 (init = enc layer0 final hidden)
    mma_gemm_kernel<<<gemm_grid_3h, 256>>>(dx, dW0i, db0i, xg, NTOK, G3H, E_);
    run_scan(dW0h, db0h, xg, hb + 2 * 2 * BH, hb + 0 * 2 * BH, 0, seqA);

    // decoder layer 1 (init = enc layer1 final hidden)
    mma_gemm_kernel<<<gemm_grid_3h, 256>>>(seqA, dW1i, db1i, xg, NTOK, G3H, H_);
    run_scan(dW1h, db1h, xg, hb + 3 * 2 * BH, hb + 1 * 2 * BH, 0, seqB);

    // final projection to vocab
    dim3 fc_grid(V_ / BN, NTOK / BM);
    mma_gemm_kernel<<<fc_grid, 256>>>(seqB, fcW, fcb, out, NTOK, V_, H_);
}